// round 15
// baseline (speedup 1.0000x reference)
#include <cuda_runtime.h>
#include <cuda_bf16.h>
#include <cstdint>

#define BATCH 16
#define CC    64
#define HID   128
#define EE    4
#define NPIX  16384
#define TPB   256
#define NCHUNK 32
#define TILES_PER_CTA 8
#define TILE_PX 64

// strides (bf16 elements)
#define SD64  72      // rows with 64 valid cols
#define SD128 136     // rows with 128 valid cols

// SMEM byte offsets (16B aligned; ldmatrix row addresses 16B aligned)
#define S_W2H 0                 // [128][136] = 34816
#define S_W2L 34816
#define S_W3H 69632             // [64][136] = 17408
#define S_W3L 87040
#define S_XW  104448            // overlay: init = W1 [128][72] hi(18432)+lo(18432)
                                //          loop  = X  [64][72]  hi(9216)+lo(9216)
#define S_H1H 141312            // [64 px][136] = 17408
#define S_H1L 158720
#define S_H2H 176128            // [64 px][136]
#define S_H2L 193536
#define S_T1  210944            // float[128]
#define S_T2  211456            // float[128]
#define S_B3  211968            // float[64]
#define SMEM_BYTES 212224

// ---------------- persistent prepped data ----------------------------------
__device__ unsigned short g_w1h[EE * 8192],  g_w1l[EE * 8192];   // [o128][i64]
__device__ unsigned short g_w2h[EE * 16384], g_w2l[EE * 16384];  // [o128][i128]
__device__ unsigned short g_w3h[EE * 8192],  g_w3l[EE * 8192];   // [c64][i128]
__device__ float g_t1[EE * HID], g_t2[EE * HID];
__device__ float g_gap[BATCH * CC];
__device__ float g_gated[BATCH * EE];

// ---------------- helpers ---------------------------------------------------
__device__ __forceinline__ uint32_t smem_u32(const void* p) {
    uint32_t a;
    asm("{ .reg .u64 t; cvta.to.shared.u64 t, %1; cvt.u32.u64 %0, t; }"
        : "=r"(a) : "l"(p));
    return a;
}
// pack (a,b) -> bf16x2 hi + bf16x2 residual-lo (a -> low half)
__device__ __forceinline__ void split2(float a, float b, uint32_t& h, uint32_t& l) {
    asm("cvt.rn.bf16x2.f32 %0, %1, %2;" : "=r"(h) : "f"(b), "f"(a));
    float ha = __uint_as_float(h << 16);
    float hb = __uint_as_float(h & 0xffff0000u);
    asm("cvt.rn.bf16x2.f32 %0, %1, %2;" : "=r"(l) : "f"(b - hb), "f"(a - ha));
}
__device__ __forceinline__ void split1(float a, unsigned short& h, unsigned short& l) {
    __nv_bfloat16 hb = __float2bfloat16(a);
    h = __bfloat16_as_ushort(hb);
    l = __bfloat16_as_ushort(__float2bfloat16(a - __bfloat162float(hb)));
}

#define LDSM4(R, ADDR) asm volatile( \
    "ldmatrix.sync.aligned.m8n8.x4.shared.b16 {%0,%1,%2,%3}, [%4];" \
    : "=r"((R)[0]), "=r"((R)[1]), "=r"((R)[2]), "=r"((R)[3]) : "r"(ADDR))
#define LDSM2(R, ADDR) asm volatile( \
    "ldmatrix.sync.aligned.m8n8.x2.shared.b16 {%0,%1}, [%2];" \
    : "=r"((R)[0]), "=r"((R)[1]) : "r"(ADDR))
#define MMA(D, A, B) asm volatile( \
    "mma.sync.aligned.m16n8k16.row.col.f32.bf16.bf16.f32 " \
    "{%0,%1,%2,%3}, {%4,%5,%6,%7}, {%8,%9}, {%0,%1,%2,%3};" \
    : "+f"((D)[0]), "+f"((D)[1]), "+f"((D)[2]), "+f"((D)[3]) \
    : "r"((A)[0]), "r"((A)[1]), "r"((A)[2]), "r"((A)[3]), "r"((B)[0]), "r"((B)[1]))

// ---------------------------------------------------------------------------
// gap: one block per (b,c) row of 16384 pixels
// ---------------------------------------------------------------------------
__global__ void gap_kernel(const float* __restrict__ x) {
    const int bc = blockIdx.x;
    const float4* p = (const float4*)(x + (size_t)bc * NPIX);
    float s = 0.f;
    for (int i = threadIdx.x; i < NPIX / 4; i += 256) {
        float4 v = p[i];
        s += (v.x + v.y) + (v.z + v.w);
    }
    #pragma unroll
    for (int o = 16; o; o >>= 1) s += __shfl_down_sync(0xffffffffu, s, o);
    __shared__ float red[8];
    if ((threadIdx.x & 31) == 0) red[threadIdx.x >> 5] = s;
    __syncthreads();
    if (threadIdx.x == 0) {
        float tot = 0.f;
        #pragma unroll
        for (int i = 0; i < 8; i++) tot += red[i];
        g_gap[bc] = tot * (1.f / NPIX);
    }
}

// ---------------------------------------------------------------------------
// gate: softmax -> top2 -> gated weights + aux loss
// ---------------------------------------------------------------------------
__global__ void gate_kernel(const float* __restrict__ gw,
                            const float* __restrict__ gb,
                            float* __restrict__ aux_out) {
    __shared__ float logit_s[BATCH][EE];
    __shared__ float gsh[BATCH][EE];
    const int t = threadIdx.x;
    if (t < BATCH * EE) {
        const int b = t >> 2, e = t & 3;
        float s = gb[e];
        const float* gp = g_gap + b * CC;
        #pragma unroll 8
        for (int c = 0; c < CC; c++) s += gp[c] * gw[e * CC + c];
        logit_s[b][e] = s;
    }
    __syncthreads();
    if (t < BATCH) {
        const int b = t;
        float l[EE];
        float mx = -1e30f;
        #pragma unroll
        for (int e = 0; e < EE; e++) { l[e] = logit_s[b][e]; mx = fmaxf(mx, l[e]); }
        float sum = 0.f;
        #pragma unroll
        for (int e = 0; e < EE; e++) { l[e] = expf(l[e] - mx); sum += l[e]; }
        #pragma unroll
        for (int e = 0; e < EE; e++) l[e] /= sum;
        int i1 = 0;
        for (int e = 1; e < EE; e++) if (l[e] > l[i1]) i1 = e;
        int i2 = -1;
        for (int e = 0; e < EE; e++) {
            if (e == i1) continue;
            if (i2 < 0 || l[e] > l[i2]) i2 = e;
        }
        const float denom = l[i1] + l[i2] + 1e-8f;
        #pragma unroll
        for (int e = 0; e < EE; e++) {
            float gv = (e == i1 || e == i2) ? l[e] / denom : 0.f;
            gsh[b][e] = gv;
            g_gated[b * EE + e] = gv;
        }
    }
    __syncthreads();
    if (t == 0) {
        float u[EE];
        float mean = 0.f;
        #pragma unroll
        for (int e = 0; e < EE; e++) {
            float s = 0.f;
            for (int b = 0; b < BATCH; b++) s += gsh[b][e];
            u[e] = s;
            mean += s;
        }
        mean *= (1.f / EE);
        float var = 0.f;
        #pragma unroll
        for (int e = 0; e < EE; e++) { float d = u[e] - mean; var += d * d; }
        var *= (1.f / EE);
        *aux_out = var / (mean * mean + 1e-10f);
    }
}

// ---------------------------------------------------------------------------
// prep: BN-fold weights, split hi/lo bf16 into device arrays (unpadded)
// ---------------------------------------------------------------------------
__global__ void prep_kernel(const float* __restrict__ W1, const float* __restrict__ b1,
                            const float* __restrict__ g1, const float* __restrict__ be1,
                            const float* __restrict__ m1, const float* __restrict__ v1,
                            const float* __restrict__ W2, const float* __restrict__ b2,
                            const float* __restrict__ g2, const float* __restrict__ be2,
                            const float* __restrict__ m2, const float* __restrict__ v2,
                            const float* __restrict__ W3) {
    const int e = blockIdx.x, t = threadIdx.x;
    __shared__ float i1[HID], i2[HID];
    if (t < HID) {
        float a = g1[e * HID + t] * rsqrtf(v1[e * HID + t] + 1e-5f);
        i1[t] = a;
        g_t1[e * HID + t] = (b1[e * HID + t] - m1[e * HID + t]) * a + be1[e * HID + t];
        float c = g2[e * HID + t] * rsqrtf(v2[e * HID + t] + 1e-5f);
        i2[t] = c;
        g_t2[e * HID + t] = (b2[e * HID + t] - m2[e * HID + t]) * c + be2[e * HID + t];
    }
    __syncthreads();
    for (int idx = t; idx < HID * CC; idx += 256) {           // W1 [o][i]
        int o = idx >> 6;
        unsigned short h, l;
        split1(W1[(size_t)e * HID * CC + idx] * i1[o], h, l);
        g_w1h[e * 8192 + idx] = h;
        g_w1l[e * 8192 + idx] = l;
    }
    for (int idx = t; idx < HID * HID; idx += 256) {          // W2 [o][i]
        int o = idx >> 7;
        unsigned short h, l;
        split1(W2[(size_t)e * HID * HID + idx] * i2[o], h, l);
        g_w2h[e * 16384 + idx] = h;
        g_w2l[e * 16384 + idx] = l;
    }
    for (int idx = t; idx < CC * HID; idx += 256) {           // W3 [c][i], no fold
        unsigned short h, l;
        split1(W3[(size_t)e * CC * HID + idx], h, l);
        g_w3h[e * 8192 + idx] = h;
        g_w3l[e * 8192 + idx] = l;
    }
}

// ---------------------------------------------------------------------------
// act-GEMM: D = A(act [px][K]) @ B(W [N][K])^T; bias+relu; split -> dst hi/lo.
// 8 warps: mg = w&1 (32 px, 2 m-tiles), ng = w>>1 (32 out chans, 4 n-tiles).
// REGB: b-side fragments (hi AND lo) come from registers (tile-invariant).
// Non-REGB b-side uses x4 pairing: one LDSM4 loads 2 n-tile fragments.
// ---------------------------------------------------------------------------
template <int KT, bool REGB>
__device__ __forceinline__ void gemm_act(
    unsigned char* smraw,
    uint32_t aH, uint32_t aL, uint32_t bH, uint32_t bL,
    int strideA, int strideB,
    const uint32_t bhf[][4][2], const uint32_t blf[][4][2],
    uint32_t dstH, uint32_t dstL, const float* biasS,
    int lane, int mg, int ng)
{
    float d[2][4][4] = {};
    const int rowA = mg * 32 + (lane & 15);
    const int colA = (lane >> 4) * 8;
    // x4-pair b addressing: lanes 0-7 -> rows+0 col+0 (b0 of nt), 8-15 -> col+8
    // (b1 of nt), 16-23 -> rows+8 col+0 (b0 of nt+1), 24-31 -> rows+8 col+8.
    const int rowP = (lane & 7) + ((lane >> 4) & 1) * 8;
    const int colP = ((lane >> 3) & 1) * 8;

    #pragma unroll
    for (int k = 0; k < KT; k++) {
        uint32_t ah0[4], ah1[4], al0[4], al1[4];
        const uint32_t a0off = (uint32_t)(rowA * strideA + k * 16 + colA) * 2;
        const uint32_t a1off = (uint32_t)((rowA + 16) * strideA + k * 16 + colA) * 2;
        LDSM4(ah0, aH + a0off);
        LDSM4(ah1, aH + a1off);
        LDSM4(al0, aL + a0off);
        LDSM4(al1, aL + a1off);
        uint32_t bh[4][2], bl[4][2];
        if (REGB) {
            #pragma unroll
            for (int nt = 0; nt < 4; nt++) {
                bh[nt][0] = bhf[k][nt][0]; bh[nt][1] = bhf[k][nt][1];
                bl[nt][0] = blf[k][nt][0]; bl[nt][1] = blf[k][nt][1];
            }
        } else {
            #pragma unroll
            for (int p = 0; p < 2; p++) {
                const uint32_t boff = (uint32_t)(
                    (ng * 32 + p * 16 + rowP) * strideB + k * 16 + colP) * 2;
                uint32_t r[4];
                LDSM4(r, bH + boff);
                bh[2 * p][0] = r[0]; bh[2 * p][1] = r[1];
                bh[2 * p + 1][0] = r[2]; bh[2 * p + 1][1] = r[3];
                LDSM4(r, bL + boff);
                bl[2 * p][0] = r[0]; bl[2 * p][1] = r[1];
                bl[2 * p + 1][0] = r[2]; bl[2 * p + 1][1] = r[3];
            }
        }
        #pragma unroll
        for (int nt = 0; nt < 4; nt++) {
            MMA(d[0][nt], ah0, bh[nt]);
            MMA(d[1][nt], ah1, bh[nt]);
        }
        #pragma unroll
        for (int nt = 0; nt < 4; nt++) {
            MMA(d[0][nt], al0, bh[nt]);
            MMA(d[1][nt], al1, bh[nt]);
        }
        #pragma unroll
        for (int nt = 0; nt < 4; nt++) {
            MMA(d[0][nt], ah0, bl[nt]);
            MMA(d[1][nt], ah1, bl[nt]);
        }
    }

    const int rbase = mg * 32 + (lane >> 2);
    #pragma unroll
    for (int mt = 0; mt < 2; mt++) {
        const int r = rbase + mt * 16;
        #pragma unroll
        for (int nt = 0; nt < 4; nt++) {
            const int n = ng * 32 + nt * 8 + (lane & 3) * 2;
            const float bx = biasS[n], by = biasS[n + 1];
            const float* dd = d[mt][nt];
            uint32_t h, l;
            split2(fmaxf(dd[0] + bx, 0.f), fmaxf(dd[1] + by, 0.f), h, l);
            *(uint32_t*)(smraw + dstH + (r * SD128 + n) * 2) = h;
            *(uint32_t*)(smraw + dstL + (r * SD128 + n) * 2) = l;
            split2(fmaxf(dd[2] + bx, 0.f), fmaxf(dd[3] + by, 0.f), h, l);
            *(uint32_t*)(smraw + dstH + ((r + 8) * SD128 + n) * 2) = h;
            *(uint32_t*)(smraw + dstL + ((r + 8) * SD128 + n) * 2) = l;
        }
    }
}

// ---------------------------------------------------------------------------
// main fused MMA kernel: one CTA per (chunk, expert, batch); 256 threads.
// 2-phase pipelined tile loop:
//   Phase A: storeX(t+1) + prefetch X(t+2) + L2(t)      [H1 -> H2]
//   Phase B: L3(t) [H2 -> out]  +  L1(t+1) [X -> H1]
// ---------------------------------------------------------------------------
__global__ __launch_bounds__(TPB, 1)
void moe_mma(const float* __restrict__ x, const float* __restrict__ b3,
             float* __restrict__ out) {
    extern __shared__ unsigned char smraw[];
    const int chunk = blockIdx.x, e = blockIdx.y, b = blockIdx.z;
    const float gval = g_gated[b * EE + e];
    if (gval == 0.f) return;

    const uint32_t sb = smem_u32(smraw);
    const int tid = threadIdx.x, w = tid >> 5, lane = tid & 31;

    // ---- copy prepped weights into padded SMEM (W1 into overlay) ----
    {
        const int4* s1h = (const int4*)(g_w1h + e * 8192);
        const int4* s1l = (const int4*)(g_w1l + e * 8192);
        for (int j = tid; j < 1024; j += TPB) {
            int o = j >> 3, cb = (j & 7) * 16;
            *(int4*)(smraw + S_XW + o * 144 + cb) = s1h[j];
            *(int4*)(smraw + S_XW + 18432 + o * 144 + cb) = s1l[j];
        }
        const int4* s2h = (const int4*)(g_w2h + e * 16384);
        const int4* s2l = (const int4*)(g_w2l + e * 16384);
        for (int j = tid; j < 2048; j += TPB) {
            int o = j >> 4, cb = (j & 15) * 16;
            *(int4*)(smraw + S_W2H + o * 272 + cb) = s2h[j];
            *(int4*)(smraw + S_W2L + o * 272 + cb) = s2l[j];
        }
        const int4* s3h = (const int4*)(g_w3h + e * 8192);
        const int4* s3l = (const int4*)(g_w3l + e * 8192);
        for (int j = tid; j < 1024; j += TPB) {
            int o = j >> 4, cb = (j & 15) * 16;
            *(int4*)(smraw + S_W3H + o * 272 + cb) = s3h[j];
            *(int4*)(smraw + S_W3L + o * 272 + cb) = s3l[j];
        }
        float* t1p = (float*)(smraw + S_T1);
        float* t2p = (float*)(smraw + S_T2);
        float* b3p = (float*)(smraw + S_B3);
        for (int i = tid; i < HID; i += TPB) {
            t1p[i] = g_t1[e * HID + i];
            t2p[i] = g_t2[e * HID + i];
        }
        for (int i = tid; i < CC; i += TPB) b3p[i] = b3[e * CC + i];
    }
    __syncthreads();

    const int mg = w & 1, ng = w >> 1;      // layers 1/2 warp tile

    // ---- hoist W1 b-side fragments (hi + lo, tile-invariant) to registers ----
    uint32_t w1fh[4][4][2], w1fl[4][4][2];
    {
        const int rowB = ng * 32 + (lane & 7);
        const int colB = ((lane >> 3) & 1) * 8;
        #pragma unroll
        for (int k = 0; k < 4; k++)
            #pragma unroll
            for (int nt = 0; nt < 4; nt++) {
                const uint32_t off =
                    (uint32_t)((rowB + nt * 8) * SD64 + k * 16 + colB) * 2;
                LDSM2(w1fh[k][nt], sb + S_XW + off);
                LDSM2(w1fl[k][nt], sb + S_XW + 18432 + off);
            }
    }
    __syncthreads();    // done reading overlay as W1; region becomes X buffer

    const float* xb = x + (size_t)b * CC * NPIX;
    float* ob = out + (size_t)b * CC * NPIX;
    const float* t1s = (const float*)(smraw + S_T1);
    const float* t2s = (const float*)(smraw + S_T2);
    const float* b3s = (const float*)(smraw + S_B3);
    const int pgbase = chunk * (TILES_PER_CTA * TILE_PX);

    // ---- X prefetch state: 16 floats per thread (2 chans x 8 px) ----
    const int c0 = (tid & 31) * 2, pb = tid >> 5;
    float4 xv0, xv1, xv2, xv3;

    // helper lambdas ---------------------------------------------------------
    auto loadX = [&](int pg0) {
        const float* r0 = xb + (size_t)c0 * NPIX + pg0 + pb * 8;
        const float* r1 = r0 + NPIX;
        xv0 = *(const float4*)(r0);
        xv1 = *(const float4*)(r0 + 4);
        xv2 = *(const float4*)(r1);
        xv3 = *(const float4*)(r1 + 4);
    };
    auto storeX = [&]() {
        const float va[8] = {xv0.x, xv0.y, xv0.z, xv0.w,
                             xv1.x, xv1.y, xv1.z, xv1.w};
        const float vb[8] = {xv2.x, xv2.y, xv2.z, xv2.w,
                             xv3.x, xv3.y, xv3.z, xv3.w};
        #pragma unroll
        for (int j = 0; j < 8; j++) {
            uint32_t h, l;
            split2(va[j], vb[j], h, l);     // (chan c0, c0+1) pair
            const int off = ((pb * 8 + j) * SD64 + c0) * 2;
            *(uint32_t*)(smraw + S_XW + off) = h;
            *(uint32_t*)(smraw + S_XW + 9216 + off) = l;
        }
    };
    auto doL1 = [&]() {
        gemm_act<4, true>(smraw, sb + S_XW, sb + S_XW + 9216, 0u, 0u,
                          SD64, SD64, w1fh, w1fl,
                          S_H1H, S_H1L, t1s, lane, mg, ng);
    };

    // ---- prologue: stage X(0), prefetch X(1), run L1(0) ----
    loadX(pgbase);
    storeX();
    if (TILES_PER_CTA > 1) loadX(pgbase + TILE_PX);
    __syncthreads();
    doL1();
    __syncthreads();

    for (int tl = 0; tl < TILES_PER_CTA; ++tl) {
        const int pg0 = pgbase + tl * TILE_PX;

        // ================= Phase A: storeX(t+1) + prefetch + L2(t) ==========
        if (tl + 1 < TILES_PER_CTA) storeX();
        if (tl + 2 < TILES_PER_CTA) loadX(pg0 + 2 * TILE_PX);
        gemm_act<8, false>(smraw, sb + S_H1H, sb + S_H1L,
                           sb + S_W2H, sb + S_W2L, SD128, SD128,
                           nullptr, nullptr,
                           S_H2H, S_H2L, t2s, lane, mg, ng);
        __syncthreads();

        // ================= Phase B: L3(t) + L1(t+1) =========================
        {
            float d[2][2][4] = {};
            const int m0 = (w & 1) * 32;
            const int n0 = (w >> 1) * 16;
            const int rowA = m0 + (lane & 15);
            const int colA = (lane >> 4) * 8;
            const int rowP = (lane & 7) + ((lane >> 4) & 1) * 8;
            const int colP = ((lane >> 3) & 1) * 8;

            #pragma unroll
            for (int k = 0; k < 8; k++) {
                uint32_t ah0[4], ah1[4], al0[4], al1[4];
                const uint32_t a0off = (uint32_t)(rowA * SD128 + k * 16 + colA) * 2;
                const uint32_t a1off =
                    (uint32_t)((rowA + 16) * SD128 + k * 16 + colA) * 2;
                LDSM4(ah0, sb + S_W3H + a0off);
                LDSM4(ah1, sb + S_W3H + a1off);
                LDSM4(al0, sb + S_W3L + a0off);
                LDSM4(al1, sb + S_W3L + a1off);
                // x4-paired B: one LDSM4 loads both n-tiles (16 px) per src
                uint32_t bh[2][2], bl[2][2];
                {
                    const uint32_t boff =
                        (uint32_t)((n0 + rowP) * SD128 + k * 16 + colP) * 2;
                    uint32_t r[4];
                    LDSM4(r, sb + S_H2H + boff);
                    bh[0][0] = r[0]; bh[0][1] = r[1];
                    bh[1][0] = r[2]; bh[1][1] = r[3];
                    LDSM4(r, sb + S_H2L + boff);
                    bl[0][0] = r[0]; bl[0][1] = r[1];
                    bl[1][0] = r[2]; bl[1][1] = r[3];
                }
                #pragma unroll
                for (int nt = 0; nt < 2; nt++) {
                    MMA(d[0][nt], ah0, bh[nt]);
                    MMA(d[1][nt], ah1, bh[nt]);
                }
                #pragma unroll
                for (int nt = 0; nt < 2; nt++) {
                    MMA(d[0][nt], al0, bh[nt]);
                    MMA(d[1][nt], al1, bh[nt]);
                }
                #pragma unroll
                for (int nt = 0; nt < 2; nt++) {
                    MMA(d[0][nt], ah0, bl[nt]);
                    MMA(d[1][nt], ah1, bl[nt]);
                }
            }
            const int rb = m0 + (lane >> 2);
            #pragma unroll
            for (int mt = 0; mt < 2; mt++) {
                const int r = rb + mt * 16;
                const float bz0 = b3s[r], bz1 = b3s[r + 8];
                #pragma unroll
                for (int nt = 0; nt < 2; nt++) {
                    const int c = n0 + nt * 8 + (lane & 3) * 2;
                    const float* dd = d[mt][nt];
                    float f0 = (dd[0] + bz0) * gval, f1 = (dd[1] + bz0) * gval;
                    float f2 = (dd[2] + bz1) * gval, f3 = (dd[3] + bz1) * gval;
                    float* p0 = ob + (size_t)r * NPIX + pg0 + c;
                    float* p1 = ob + (size_t)(r + 8) * NPIX + pg0 + c;
                    asm volatile("red.global.add.v2.f32 [%0], {%1,%2};"
                                 :: "l"(p0), "f"(f0), "f"(f1) : "memory");
                    asm volatile("red.global.add.v2.f32 [%0], {%1,%2};"
                                 :: "l"(p1), "f"(f2), "f"(f3) : "memory");
                }
            }
        }
        if (tl + 1 < TILES_PER_CTA) doL1();   // L1(t+1): X -> H1 (same phase)
        __syncthreads();
    }
}

// ---------------------------------------------------------------------------
extern "C" void kernel_launch(void* const* d_in, const int* in_sizes, int n_in,
                              void* d_out, int out_size) {
    const float* x   = (const float*)d_in[0];
    const float* W1  = (const float*)d_in[1];
    const float* b1  = (const float*)d_in[2];
    const float* g1  = (const float*)d_in[3];
    const float* be1 = (const float*)d_in[4];
    const float* m1  = (const float*)d_in[5];
    const float* v1  = (const float*)d_in[6];
    const float* W2  = (const float*)d_in[7];
    const float* b2  = (const float*)d_in[8];
    const float* g2  = (const float*)d_in[9];
    const float* be2 = (const float*)d_in[10];
    const float* m2  = (const float*)d_in[11];
    const float* v2  = (const float*)d_in[12];
    const float* W3  = (const float*)d_in[13];
    const float* b3  = (const float*)d_in[14];
    const float* gw  = (const float*)d_in[15];
    const float* gb  = (const float*)d_in[16];
    float* out = (float*)d_out;

    cudaMemsetAsync(out, 0, (size_t)(out_size - 1) * sizeof(float), 0);
    gap_kernel<<<BATCH * CC, 256>>>(x);
    gate_kernel<<<1, 64>>>(gw, gb, out + (out_size - 1));
    prep_kernel<<<EE, 256>>>(W1, b1, g1, be1, m1, v1,
                             W2, b2, g2, be2, m2, v2, W3);

    cudaFuncSetAttribute(moe_mma, cudaFuncAttributeMaxDynamicSharedMemorySize,
                         SMEM_BYTES);
    dim3 grid(NCHUNK, EE, BATCH);
    moe_mma<<<grid, TPB, SMEM_BYTES>>>(x, b3, out);
}

// round 17
// speedup vs baseline: 1.1497x; 1.1497x over previous
#include <cuda_runtime.h>
#include <cuda_fp16.h>
#include <cstdint>

#define BATCH 16
#define CC    64
#define HID   128
#define EE    4
#define NPIX  16384
#define TPB   256
#define NCHUNK 32
#define TILES_PER_CTA 8
#define TILE_PX 64

// strides (fp16 elements)
#define SD64  72      // rows with 64 valid cols
#define SD128 136     // rows with 128 valid cols

// SMEM byte offsets (16B aligned; ldmatrix row addresses 16B aligned)
#define S_W2H 0                 // [128][136] = 34816 (hi only)
#define S_W3H 34816             // [64][136] = 17408
#define S_W3L 52224             // [64][136] = 17408 (A-side lo kept for L3)
#define S_XW  69632             // overlay: init = W1 hi [128][72] = 18432
                                //          loop  = X hi(9216) + X lo(9216)
#define S_H1H 88064             // [64 px][136] = 17408
#define S_H1L 105472            // H1 lo (A-side of L2)
#define S_H2H 122880            // hi only (L3 B-side)
#define S_T1  140288            // float[128]
#define S_T2  140800            // float[128]
#define S_B3  141312            // float[64]
#define SMEM_BYTES 141568

// ---------------- persistent prepped data ----------------------------------
__device__ unsigned short g_w1h[EE * 8192];                      // [o128][i64]
__device__ unsigned short g_w2h[EE * 16384];                     // [o128][i128]
__device__ unsigned short g_w3h[EE * 8192], g_w3l[EE * 8192];    // [c64][i128]
__device__ float g_t1[EE * HID], g_t2[EE * HID];
__device__ float g_gap[BATCH * CC];
__device__ float g_gated[BATCH * EE];

// ---------------- helpers ---------------------------------------------------
__device__ __forceinline__ uint32_t smem_u32(const void* p) {
    uint32_t a;
    asm("{ .reg .u64 t; cvta.to.shared.u64 t, %1; cvt.u32.u64 %0, t; }"
        : "=r"(a) : "l"(p));
    return a;
}
// pack (a,b) -> f16x2 hi + f16x2 residual-lo (a -> low half)
__device__ __forceinline__ void split2(float a, float b, uint32_t& h, uint32_t& l) {
    asm("cvt.rn.f16x2.f32 %0, %1, %2;" : "=r"(h) : "f"(b), "f"(a));
    __half2 hv = *reinterpret_cast<__half2*>(&h);
    float2 f = __half22float2(hv);
    asm("cvt.rn.f16x2.f32 %0, %1, %2;" : "=r"(l) : "f"(b - f.y), "f"(a - f.x));
}
__device__ __forceinline__ uint32_t pack2h(float a, float b) {
    uint32_t h;
    asm("cvt.rn.f16x2.f32 %0, %1, %2;" : "=r"(h) : "f"(b), "f"(a));
    return h;
}
__device__ __forceinline__ void split1(float a, unsigned short& h, unsigned short& l) {
    __half hh = __float2half_rn(a);
    h = __half_as_ushort(hh);
    l = __half_as_ushort(__float2half_rn(a - __half2float(hh)));
}

#define LDSM4(R, ADDR) asm volatile( \
    "ldmatrix.sync.aligned.m8n8.x4.shared.b16 {%0,%1,%2,%3}, [%4];" \
    : "=r"((R)[0]), "=r"((R)[1]), "=r"((R)[2]), "=r"((R)[3]) : "r"(ADDR))
#define LDSM2(R, ADDR) asm volatile( \
    "ldmatrix.sync.aligned.m8n8.x2.shared.b16 {%0,%1}, [%2];" \
    : "=r"((R)[0]), "=r"((R)[1]) : "r"(ADDR))
#define MMA(D, A, B) asm volatile( \
    "mma.sync.aligned.m16n8k16.row.col.f32.f16.f16.f32 " \
    "{%0,%1,%2,%3}, {%4,%5,%6,%7}, {%8,%9}, {%0,%1,%2,%3};" \
    : "+f"((D)[0]), "+f"((D)[1]), "+f"((D)[2]), "+f"((D)[3]) \
    : "r"((A)[0]), "r"((A)[1]), "r"((A)[2]), "r"((A)[3]), "r"((B)[0]), "r"((B)[1]))

// ---------------------------------------------------------------------------
// gap: one block per (b,c) row of 16384 pixels
// ---------------------------------------------------------------------------
__global__ void gap_kernel(const float* __restrict__ x) {
    const int bc = blockIdx.x;
    const float4* p = (const float4*)(x + (size_t)bc * NPIX);
    float s = 0.f;
    for (int i = threadIdx.x; i < NPIX / 4; i += 256) {
        float4 v = p[i];
        s += (v.x + v.y) + (v.z + v.w);
    }
    #pragma unroll
    for (int o = 16; o; o >>= 1) s += __shfl_down_sync(0xffffffffu, s, o);
    __shared__ float red[8];
    if ((threadIdx.x & 31) == 0) red[threadIdx.x >> 5] = s;
    __syncthreads();
    if (threadIdx.x == 0) {
        float tot = 0.f;
        #pragma unroll
        for (int i = 0; i < 8; i++) tot += red[i];
        g_gap[bc] = tot * (1.f / NPIX);
    }
}

// ---------------------------------------------------------------------------
// gate: softmax -> top2 -> gated weights + aux loss
// ---------------------------------------------------------------------------
__global__ void gate_kernel(const float* __restrict__ gw,
                            const float* __restrict__ gb,
                            float* __restrict__ aux_out) {
    __shared__ float logit_s[BATCH][EE];
    __shared__ float gsh[BATCH][EE];
    const int t = threadIdx.x;
    if (t < BATCH * EE) {
        const int b = t >> 2, e = t & 3;
        float s = gb[e];
        const float* gp = g_gap + b * CC;
        #pragma unroll 8
        for (int c = 0; c < CC; c++) s += gp[c] * gw[e * CC + c];
        logit_s[b][e] = s;
    }
    __syncthreads();
    if (t < BATCH) {
        const int b = t;
        float l[EE];
        float mx = -1e30f;
        #pragma unroll
        for (int e = 0; e < EE; e++) { l[e] = logit_s[b][e]; mx = fmaxf(mx, l[e]); }
        float sum = 0.f;
        #pragma unroll
        for (int e = 0; e < EE; e++) { l[e] = expf(l[e] - mx); sum += l[e]; }
        #pragma unroll
        for (int e = 0; e < EE; e++) l[e] /= sum;
        int i1 = 0;
        for (int e = 1; e < EE; e++) if (l[e] > l[i1]) i1 = e;
        int i2 = -1;
        for (int e = 0; e < EE; e++) {
            if (e == i1) continue;
            if (i2 < 0 || l[e] > l[i2]) i2 = e;
        }
        const float denom = l[i1] + l[i2] + 1e-8f;
        #pragma unroll
        for (int e = 0; e < EE; e++) {
            float gv = (e == i1 || e == i2) ? l[e] / denom : 0.f;
            gsh[b][e] = gv;
            g_gated[b * EE + e] = gv;
        }
    }
    __syncthreads();
    if (t == 0) {
        float u[EE];
        float mean = 0.f;
        #pragma unroll
        for (int e = 0; e < EE; e++) {
            float s = 0.f;
            for (int b = 0; b < BATCH; b++) s += gsh[b][e];
            u[e] = s;
            mean += s;
        }
        mean *= (1.f / EE);
        float var = 0.f;
        #pragma unroll
        for (int e = 0; e < EE; e++) { float d = u[e] - mean; var += d * d; }
        var *= (1.f / EE);
        *aux_out = var / (mean * mean + 1e-10f);
    }
}

// ---------------------------------------------------------------------------
// prep: BN-fold weights, split fp16 hi/lo into device arrays (unpadded)
// ---------------------------------------------------------------------------
__global__ void prep_kernel(const float* __restrict__ W1, const float* __restrict__ b1,
                            const float* __restrict__ g1, const float* __restrict__ be1,
                            const float* __restrict__ m1, const float* __restrict__ v1,
                            const float* __restrict__ W2, const float* __restrict__ b2,
                            const float* __restrict__ g2, const float* __restrict__ be2,
                            const float* __restrict__ m2, const float* __restrict__ v2,
                            const float* __restrict__ W3) {
    const int e = blockIdx.x, t = threadIdx.x;
    __shared__ float i1[HID], i2[HID];
    if (t < HID) {
        float a = g1[e * HID + t] * rsqrtf(v1[e * HID + t] + 1e-5f);
        i1[t] = a;
        g_t1[e * HID + t] = (b1[e * HID + t] - m1[e * HID + t]) * a + be1[e * HID + t];
        float c = g2[e * HID + t] * rsqrtf(v2[e * HID + t] + 1e-5f);
        i2[t] = c;
        g_t2[e * HID + t] = (b2[e * HID + t] - m2[e * HID + t]) * c + be2[e * HID + t];
    }
    __syncthreads();
    for (int idx = t; idx < HID * CC; idx += 256) {           // W1 [o][i] hi only
        int o = idx >> 6;
        g_w1h[e * 8192 + idx] = __half_as_ushort(
            __float2half_rn(W1[(size_t)e * HID * CC + idx] * i1[o]));
    }
    for (int idx = t; idx < HID * HID; idx += 256) {          // W2 [o][i] hi only
        int o = idx >> 7;
        g_w2h[e * 16384 + idx] = __half_as_ushort(
            __float2half_rn(W2[(size_t)e * HID * HID + idx] * i2[o]));
    }
    for (int idx = t; idx < CC * HID; idx += 256) {           // W3 [c][i] hi+lo
        unsigned short h, l;
        split1(W3[(size_t)e * CC * HID + idx], h, l);
        g_w3h[e * 8192 + idx] = h;
        g_w3l[e * 8192 + idx] = l;
    }
}

// ---------------------------------------------------------------------------
// act-GEMM: D = A(act [px][K] hi+lo) @ B(W [N][K] hi)^T ; 2-pass fp16x2.
// bias+relu; WRLO: write dst hi+lo (stride SD128) else hi only.
// 8 warps: mg = w&1 (32 px, 2 m-tiles), ng = w>>1 (32 out chans, 4 n-tiles).
// REGB: b-side fragments come from registers (tile-invariant).
// ---------------------------------------------------------------------------
template <int KT, bool REGB, bool WRLO>
__device__ __forceinline__ void gemm_act(
    unsigned char* smraw,
    uint32_t aH, uint32_t aL, uint32_t bH,
    int strideA, int strideB,
    const uint32_t bhf[][4][2],
    uint32_t dstH, uint32_t dstL, const float* biasS,
    int lane, int mg, int ng)
{
    float d[2][4][4] = {};
    const int rowA = mg * 32 + (lane & 15);
    const int colA = (lane >> 4) * 8;
    const int rowB = ng * 32 + (lane & 7);
    const int colB = ((lane >> 3) & 1) * 8;

    #pragma unroll
    for (int k = 0; k < KT; k++) {
        uint32_t ah0[4], ah1[4], al0[4], al1[4];
        const uint32_t a0off = (uint32_t)(rowA * strideA + k * 16 + colA) * 2;
        const uint32_t a1off = (uint32_t)((rowA + 16) * strideA + k * 16 + colA) * 2;
        LDSM4(ah0, aH + a0off);
        LDSM4(ah1, aH + a1off);
        LDSM4(al0, aL + a0off);
        LDSM4(al1, aL + a1off);
        uint32_t bh[4][2];
        #pragma unroll
        for (int nt = 0; nt < 4; nt++) {
            if (REGB) {
                bh[nt][0] = bhf[k][nt][0]; bh[nt][1] = bhf[k][nt][1];
            } else {
                const uint32_t boff =
                    (uint32_t)((rowB + nt * 8) * strideB + k * 16 + colB) * 2;
                LDSM2(bh[nt], bH + boff);
            }
        }
        #pragma unroll
        for (int nt = 0; nt < 4; nt++) {
            MMA(d[0][nt], ah0, bh[nt]);
            MMA(d[1][nt], ah1, bh[nt]);
        }
        #pragma unroll
        for (int nt = 0; nt < 4; nt++) {
            MMA(d[0][nt], al0, bh[nt]);
            MMA(d[1][nt], al1, bh[nt]);
        }
    }

    const int rbase = mg * 32 + (lane >> 2);
    #pragma unroll
    for (int mt = 0; mt < 2; mt++) {
        const int r = rbase + mt * 16;
        #pragma unroll
        for (int nt = 0; nt < 4; nt++) {
            const int n = ng * 32 + nt * 8 + (lane & 3) * 2;
            const float bx = biasS[n], by = biasS[n + 1];
            const float* dd = d[mt][nt];
            const float v0 = fmaxf(dd[0] + bx, 0.f), v1 = fmaxf(dd[1] + by, 0.f);
            const float v2 = fmaxf(dd[2] + bx, 0.f), v3 = fmaxf(dd[3] + by, 0.f);
            if (WRLO) {
                uint32_t h, l;
                split2(v0, v1, h, l);
                *(uint32_t*)(smraw + dstH + (r * SD128 + n) * 2) = h;
                *(uint32_t*)(smraw + dstL + (r * SD128 + n) * 2) = l;
                split2(v2, v3, h, l);
                *(uint32_t*)(smraw + dstH + ((r + 8) * SD128 + n) * 2) = h;
                *(uint32_t*)(smraw + dstL + ((r + 8) * SD128 + n) * 2) = l;
            } else {
                *(uint32_t*)(smraw + dstH + (r * SD128 + n) * 2) = pack2h(v0, v1);
                *(uint32_t*)(smraw + dstH + ((r + 8) * SD128 + n) * 2) = pack2h(v2, v3);
            }
        }
    }
}

// ---------------------------------------------------------------------------
// main fused MMA kernel: one CTA per (chunk, expert, batch); 256 threads.
// 2-phase pipelined tile loop:
//   Phase A: storeX(t+1) + prefetch X(t+2) + L2(t)      [H1 -> H2]
//   Phase B: L3(t) [H2 -> out]  +  L1(t+1) [X -> H1]
// ---------------------------------------------------------------------------
__global__ __launch_bounds__(TPB, 1)
void moe_mma(const float* __restrict__ x, const float* __restrict__ b3,
             float* __restrict__ out) {
    extern __shared__ unsigned char smraw[];
    const int chunk = blockIdx.x, e = blockIdx.y, b = blockIdx.z;
    const float gval = g_gated[b * EE + e];
    if (gval == 0.f) return;

    const uint32_t sb = smem_u32(smraw);
    const int tid = threadIdx.x, w = tid >> 5, lane = tid & 31;

    // ---- copy prepped weights into padded SMEM (W1 hi into overlay) ----
    {
        const int4* s1h = (const int4*)(g_w1h + e * 8192);
        for (int j = tid; j < 1024; j += TPB) {
            int o = j >> 3, cb = (j & 7) * 16;
            *(int4*)(smraw + S_XW + o * 144 + cb) = s1h[j];
        }
        const int4* s2h = (const int4*)(g_w2h + e * 16384);
        for (int j = tid; j < 2048; j += TPB) {
            int o = j >> 4, cb = (j & 15) * 16;
            *(int4*)(smraw + S_W2H + o * 272 + cb) = s2h[j];
        }
        const int4* s3h = (const int4*)(g_w3h + e * 8192);
        const int4* s3l = (const int4*)(g_w3l + e * 8192);
        for (int j = tid; j < 1024; j += TPB) {
            int o = j >> 4, cb = (j & 15) * 16;
            *(int4*)(smraw + S_W3H + o * 272 + cb) = s3h[j];
            *(int4*)(smraw + S_W3L + o * 272 + cb) = s3l[j];
        }
        float* t1p = (float*)(smraw + S_T1);
        float* t2p = (float*)(smraw + S_T2);
        float* b3p = (float*)(smraw + S_B3);
        for (int i = tid; i < HID; i += TPB) {
            t1p[i] = g_t1[e * HID + i];
            t2p[i] = g_t2[e * HID + i];
        }
        for (int i = tid; i < CC; i += TPB) b3p[i] = b3[e * CC + i];
    }
    __syncthreads();

    const int mg = w & 1, ng = w >> 1;      // layers 1/2 warp tile

    // ---- hoist W1 b-side fragments (hi, tile-invariant) to registers ----
    uint32_t w1fh[4][4][2];
    {
        const int rowB = ng * 32 + (lane & 7);
        const int colB = ((lane >> 3) & 1) * 8;
        #pragma unroll
        for (int k = 0; k < 4; k++)
            #pragma unroll
            for (int nt = 0; nt < 4; nt++) {
                const uint32_t off =
                    (uint32_t)((rowB + nt * 8) * SD64 + k * 16 + colB) * 2;
                LDSM2(w1fh[k][nt], sb + S_XW + off);
            }
    }
    __syncthreads();    // done reading overlay as W1; region becomes X buffer

    const float* xb = x + (size_t)b * CC * NPIX;
    float* ob = out + (size_t)b * CC * NPIX;
    const float* t1s = (const float*)(smraw + S_T1);
    const float* t2s = (const float*)(smraw + S_T2);
    const float* b3s = (const float*)(smraw + S_B3);
    const int pgbase = chunk * (TILES_PER_CTA * TILE_PX);

    // ---- X prefetch state: 16 floats per thread (2 chans x 8 px) ----
    const int c0 = (tid & 31) * 2, pb = tid >> 5;
    float4 xv0, xv1, xv2, xv3;

    // helper lambdas ---------------------------------------------------------
    auto loadX = [&](int pg0) {
        const float* r0 = xb + (size_t)c0 * NPIX + pg0 + pb * 8;
        const float* r1 = r0 + NPIX;
        xv0 = *(const float4*)(r0);
        xv1 = *(const float4*)(r0 + 4);
        xv2 = *(const float4*)(r1);
        xv3 = *(const float4*)(r1 + 4);
    };
    auto storeX = [&]() {
        const float va[8] = {xv0.x, xv0.y, xv0.z, xv0.w,
                             xv1.x, xv1.y, xv1.z, xv1.w};
        const float vb[8] = {xv2.x, xv2.y, xv2.z, xv2.w,
                             xv3.x, xv3.y, xv3.z, xv3.w};
        #pragma unroll
        for (int j = 0; j < 8; j++) {
            uint32_t h, l;
            split2(va[j], vb[j], h, l);     // (chan c0, c0+1) pair
            const int off = ((pb * 8 + j) * SD64 + c0) * 2;
            *(uint32_t*)(smraw + S_XW + off) = h;
            *(uint32_t*)(smraw + S_XW + 9216 + off) = l;
        }
    };
    auto doL1 = [&]() {
        gemm_act<4, true, true>(smraw, sb + S_XW, sb + S_XW + 9216, 0u,
                                SD64, SD64, w1fh,
                                S_H1H, S_H1L, t1s, lane, mg, ng);
    };

    // ---- prologue: stage X(0), prefetch X(1), run L1(0) ----
    loadX(pgbase);
    storeX();
    if (TILES_PER_CTA > 1) loadX(pgbase + TILE_PX);
    __syncthreads();
    doL1();
    __syncthreads();

    for (int tl = 0; tl < TILES_PER_CTA; ++tl) {
        const int pg0 = pgbase + tl * TILE_PX;

        // ================= Phase A: storeX(t+1) + prefetch + L2(t) ==========
        if (tl + 1 < TILES_PER_CTA) storeX();
        if (tl + 2 < TILES_PER_CTA) loadX(pg0 + 2 * TILE_PX);
        gemm_act<8, false, false>(smraw, sb + S_H1H, sb + S_H1L,
                                  sb + S_W2H, SD128, SD128, nullptr,
                                  S_H2H, 0u, t2s, lane, mg, ng);
        __syncthreads();

        // ================= Phase B: L3(t) + L1(t+1) =========================
        // L3: A = W3 (hi+lo, 2-pass), B = H2 hi.
        {
            float d[2][2][4] = {};
            const int m0 = (w & 1) * 32;
            const int n0 = (w >> 1) * 16;
            const int rowA = m0 + (lane & 15);
            const int colA = (lane >> 4) * 8;
            const int rowB = n0 + (lane & 7);
            const int colB = ((lane >> 3) & 1) * 8;

            #pragma unroll
            for (int k = 0; k < 8; k++) {
                uint32_t ah0[4], ah1[4], al0[4], al1[4];
                const uint32_t a0off = (uint32_t)(rowA * SD128 + k * 16 + colA) * 2;
                const uint32_t a1off =
                    (uint32_t)((rowA + 16) * SD128 + k * 16 + colA) * 2;
                LDSM4(ah0, sb + S_W3H + a0off);
                LDSM4(ah1, sb + S_W3H + a1off);
                LDSM4(al0, sb + S_W3L + a0off);
                LDSM4(al1, sb + S_W3L + a1off);
                uint32_t bh[2][2];
                #pragma unroll
                for (int nt = 0; nt < 2; nt++) {
                    const uint32_t boff =
                        (uint32_t)((rowB + nt * 8) * SD128 + k * 16 + colB) * 2;
                    LDSM2(bh[nt], sb + S_H2H + boff);
                }
                #pragma unroll
                for (int nt = 0; nt < 2; nt++) {
                    MMA(d[0][nt], ah0, bh[nt]);
                    MMA(d[1][nt], ah1, bh[nt]);
                }
                #pragma unroll
                for (int nt = 0; nt < 2; nt++) {
                    MMA(d[0][nt], al0, bh[nt]);
                    MMA(d[1][nt], al1, bh[nt]);
                }
            }
            const int rb = m0 + (lane >> 2);
            #pragma unroll
            for (int mt = 0; mt < 2; mt++) {
                const int r = rb + mt * 16;
                const float bz0 = b3s[r], bz1 = b3s[r + 8];
                #pragma unroll
                for (int nt = 0; nt < 2; nt++) {
                    const int c = n0 + nt * 8 + (lane & 3) * 2;
                    const float* dd = d[mt][nt];
                    float f0 = (dd[0] + bz0) * gval, f1 = (dd[1] + bz0) * gval;
                    float f2 = (dd[2] + bz1) * gval, f3 = (dd[3] + bz1) * gval;
                    float* p0 = ob + (size_t)r * NPIX + pg0 + c;
                    float* p1 = ob + (size_t)(r + 8) * NPIX + pg0 + c;
                    asm volatile("red.global.add.v2.f32 [%0], {%1,%2};"
                                 :: "l"(p0), "f"(f0), "f"(f1) : "memory");
                    asm volatile("red.global.add.v2.f32 [%0], {%1,%2};"
                                 :: "l"(p1), "f"(f2), "f"(f3) : "memory");
                }
            }
        }
        if (tl + 1 < TILES_PER_CTA) doL1();   // L1(t+1): X -> H1 (same phase)
        __syncthreads();
    }
}

// ---------------------------------------------------------------------------
extern "C" void kernel_launch(void* const* d_in, const int* in_sizes, int n_in,
                              void* d_out, int out_size) {
    const float* x   = (const float*)d_in[0];
    const float* W1  = (const float*)d_in[1];
    const float* b1  = (const float*)d_in[2];
    const float* g1  = (const float*)d_in[3];
    const float* be1 = (const float*)d_in[4];
    const float* m1  = (const float*)d_in[5];
    const float* v1  = (const float*)d_in[6];
    const float* W2  = (const float*)d_in[7];
    const float* b2  = (const float*)d_in[8];
    const float* g2  = (const float*)d_in[9];
    const float* be2 = (const float*)d_in[10];
    const float* m2  = (const float*)d_in[11];
    const float* v2  = (const float*)d_in[12];
    const float* W3  = (const float*)d_in[13];
    const float* b3  = (const float*)d_in[14];
    const float* gw  = (const float*)d_in[15];
    const float* gb  = (const float*)d_in[16];
    float* out = (float*)d_out;

    cudaMemsetAsync(out, 0, (size_t)(out_size - 1) * sizeof(float), 0);
    gap_kernel<<<BATCH * CC, 256>>>(x);
    gate_kernel<<<1, 64>>>(gw, gb, out + (out_size - 1));
    prep_kernel<<<EE, 256>>>(W1, b1, g1, be1, m1, v1,
                             W2, b2, g2, be2, m2, v2, W3);

    cudaFuncSetAttribute(moe_mma, cudaFuncAttributeMaxDynamicSharedMemorySize,
                         SMEM_BYTES);
    dim3 grid(NCHUNK, EE, BATCH);
    moe_mma<<<grid, TPB, SMEM_BYTES>>>(x, b3, out);
}